// round 6
// baseline (speedup 1.0000x reference)
#include <cuda_runtime.h>
#include <math_constants.h>

#define MDATA 250000
#define NPH 4
#define NK 6
#define NMC 64
#define KN (NK*NMC)            // 384
#define NROWS (NPH+NK)

#define NUI 192
#define NVI 32
#define NUN (NUI+1)            // 193
#define NVN (NVI+1)            // 33
#define NODES (NUN*NVN)        // 6369 -> 99.5 KB table

#define V0C 0.01f
#define HUC (1.0f/192.0f)
#define HVC (0.3f/32.0f)

#define TPB 1024
#define NBLK 152               // = GB300 SM count; 1 block/SM guaranteed (full RF)

__device__ float4 g_table[NODES];
__device__ float  g_partials[NBLK];
__device__ unsigned int g_sync  = 0;
__device__ unsigned int g_count = 0;

// ---------------------------------------------------------------------------
// Single fused persistent kernel:
//   phase 0: per-block (k,n) constants into shared (redundant, parallel)
//   phase 1: grid-wide table build -> g_table, device spin barrier
//   phase 2: per-point bicubic Hermite from L2 + fused deterministic reduce
// ---------------------------------------------------------------------------
__global__ void __launch_bounds__(TPB, 1) bimm_fused_kernel(
    const float* __restrict__ gu, const float* __restrict__ gv,
    const float* __restrict__ geps, const float* __restrict__ gI,
    const float* __restrict__ gW,  const float* __restrict__ gsb,
    const float* __restrict__ gsn, const float* __restrict__ gd,
    const float* __restrict__ gr,  float* __restrict__ out)
{
    __shared__ float4 skn[KN];     // (B*IE, A'*IE, C*IE, B) per (k,n)
    __shared__ float2 sint[NPH];   // (alpha, beta) nats, weights folded
    __shared__ float  sRed[TPB / 32];
    __shared__ bool   s_last;

    const int tid  = threadIdx.x;
    const int wid  = tid >> 5;
    const int lane = tid & 31;
    const float IE  = 1.44269504088896340736f;
    const float LN2 = 0.69314718055994530942f;

    // ---- scalars (every thread) ----
    const float sb  = gsb[0];
    const float sn  = gsn[0];
    const float dd  = gd[0];
    const float rho = tanhf(gr[0]);
    const float omr = 1.0f - rho;
    const float s2  = sn * sn * omr;
    const float sr  = sn * sqrtf(omr);
    const float isn2 = 1.0f / (sn * sn);
    const float k_u = -0.5f * IE * isn2;
    const float k_v = -IE / s2;

    // ---- phase 0: constants into shared ----
    if (tid < KN) {
        // log-softmax normalizer (redundant per thread; 10 exp)
        float mw = -CUDART_INF_F;
        #pragma unroll
        for (int j = 0; j < NROWS; j++) mw = fmaxf(mw, gW[j]);
        float sw = 0.0f;
        #pragma unroll
        for (int j = 0; j < NROWS; j++) sw += expf(gW[j] - mw);
        float lse = mw + logf(sw);

        float cCn = -logf(sn * sr * CUDART_PI_F * 1.41421356237f)
                    - logf((float)NMC);

        const int IAc[NK] = {0,0,0,1,1,2};
        const int IBc[NK] = {1,2,3,2,3,3};
        int k = tid >> 6;
        float Ia = gI[IAc[k]];
        float Ib = gI[IBc[k]];
        float dI = Ib - Ia;
        float gc = dI * rsqrtf(2.0f * CUDART_PI_F * sb * sb);
        float x  = geps[tid] * (2.0f * dd * sb) - dd * sb;
        float z  = x / (1.41421356237309515f * sb);
        float In = (erff(z) + 1.0f) * 0.5f * dI + Ia;
        float G  = gc * expf(-z * z);            // erfinv(erf(z)) == z
        float B  = In * isn2;
        float Ap = -0.5f * In * In * isn2 - G * G / s2 - logf(G)
                   + cCn + (gW[NPH + k] - lse);
        float C  = 2.0f * G / s2;
        skn[tid] = make_float4(B * IE, Ap * IE, C * IE, B);

        if (tid < NPH) {
            float cIn = 0.69314718056f + 0.12078223764f
                        - 3.0f * logf(sr) - logf(sn) - 0.5f * 1.83787706641f;
            float Ip = gI[tid];
            sint[tid] = make_float2(Ip * isn2,
                                    -0.5f * Ip * Ip * isn2 + cIn + (gW[tid] - lse));
        }
    }
    __syncthreads();

    // ---- phase 1: build table nodes (one warp per node) ----
    for (int node = blockIdx.x * (TPB / 32) + wid; node < NODES;
         node += NBLK * (TPB / 32)) {
        int iu = node / NVN;
        int iv = node - iu * NVN;
        float u = iu * HUC;
        float v = V0C + iv * HVC;
        float inv_v = 1.0f / v;

        float sT = 0.f, sTu = 0.f, sTv = 0.f, sTuv = 0.f;
        #pragma unroll
        for (int t = 0; t < KN / 32; t++) {
            float4 c = skn[lane + (t << 5)];
            float qh = exp2f(fmaf(u, c.x, c.y));     // exp(uB + A')
            float xn = c.z * v;                      // C*v (log2 units)
            float ex  = exp2f(xn);
            float iex = exp2f(-xn);
            float sh = ex - iex;                     // 2 sinh(Cv)
            float ch = ex + iex;                     // 2 cosh(Cv)
            float Cn = c.z * LN2;                    // C (nats)
            float tv = fmaf(Cn, ch, -sh * inv_v);
            float qs = qh * sh;
            float qt = qh * tv;
            sT   += qs;
            sTv  += qt;
            sTu  = fmaf(qs, c.w, sTu);
            sTuv = fmaf(qt, c.w, sTuv);
        }
        #pragma unroll
        for (int o = 16; o; o >>= 1) {
            sT   += __shfl_xor_sync(0xffffffffu, sT,   o);
            sTu  += __shfl_xor_sync(0xffffffffu, sTu,  o);
            sTv  += __shfl_xor_sync(0xffffffffu, sTv,  o);
            sTuv += __shfl_xor_sync(0xffffffffu, sTuv, o);
        }
        if (lane == 0) {
            float T   = sT   * inv_v;
            float Tu  = sTu  * inv_v;
            float Tv  = sTv  * inv_v;
            float Tuv = sTuv * inv_v;
            #pragma unroll
            for (int p = 0; p < NPH; p++) {
                float2 ab = sint[p];
                float tp = expf(fmaf(u, ab.x, ab.y));
                T  += tp;
                Tu = fmaf(ab.x, tp, Tu);
            }
            float invT = 1.0f / T;
            float hu = Tu * invT;
            float hv = Tv * invT;
            float4 o;
            o.x = log2f(T);
            o.y = hu * IE;
            o.z = hv * IE;
            o.w = (Tuv * invT - hu * hv) * IE;
            g_table[node] = o;
        }
    }

    // ---- device-wide barrier (all 152 blocks are co-resident) ----
    if (tid == 0) {
        __threadfence();
        atomicAdd(&g_sync, 1u);
        while (atomicAdd(&g_sync, 0u) < NBLK) __nanosleep(64);
    }
    __syncthreads();
    __threadfence();

    // ---- phase 2: per-point bicubic Hermite (table via L2) ----
    float acc = 0.0f;
    for (int m = blockIdx.x * TPB + tid; m < MDATA; m += NBLK * TPB) {
        float u = gu[m];
        float v = gv[m];
        float l2v = log2f(v);
        float pm = k_u * u * u + k_v * v * v + 2.0f * l2v;

        float su = u * (float)NUI;
        int iu = (int)su; iu = min(max(iu, 0), NUI - 1);
        float s = su - (float)iu;
        float sv = (v - V0C) * ((float)NVI / 0.3f);
        int iv = (int)sv; iv = min(max(iv, 0), NVI - 1);
        float t = sv - (float)iv;

        const float4* tb = g_table + (iu * NVN + iv);
        float4 c00 = __ldg(tb);
        float4 c01 = __ldg(tb + 1);
        float4 c10 = __ldg(tb + NVN);
        float4 c11 = __ldg(tb + NVN + 1);

        float ss = s * s, s3 = ss * s;
        float Au0 = 2.0f * s3 - 3.0f * ss + 1.0f;
        float Au1 = (s3 - 2.0f * ss + s) * HUC;
        float Au2 = 3.0f * ss - 2.0f * s3;
        float Au3 = (s3 - ss) * HUC;
        float tt = t * t, t3 = tt * t;
        float Av0 = 2.0f * t3 - 3.0f * tt + 1.0f;
        float Av1 = (t3 - 2.0f * tt + t) * HVC;
        float Av2 = 3.0f * tt - 2.0f * t3;
        float Av3 = (t3 - tt) * HVC;

        float P0 = Av0*c00.x + Av1*c00.z + Av2*c01.x + Av3*c01.z;
        float P1 = Av0*c00.y + Av1*c00.w + Av2*c01.y + Av3*c01.w;
        float P2 = Av0*c10.x + Av1*c10.z + Av2*c11.x + Av3*c11.z;
        float P3 = Av0*c10.y + Av1*c10.w + Av2*c11.y + Av3*c11.w;
        float f  = Au0*P0 + Au1*P1 + Au2*P2 + Au3*P3;

        acc += pm + f;
    }

    // ---- deterministic block + grid reduction ----
    #pragma unroll
    for (int o = 16; o > 0; o >>= 1) acc += __shfl_down_sync(0xffffffffu, acc, o);
    if (lane == 0) sRed[wid] = acc;
    __syncthreads();
    if (tid == 0) {
        float bs = 0.0f;
        #pragma unroll
        for (int w = 0; w < TPB / 32; w++) bs += sRed[w];
        g_partials[blockIdx.x] = bs;
        __threadfence();
        unsigned int ticket = atomicAdd(&g_count, 1u);
        s_last = (ticket == NBLK - 1);
    }
    __syncthreads();

    if (s_last) {
        float a = 0.0f;
        if (tid < 32) {
            for (int i = tid; i < NBLK; i += 32) a += g_partials[i];
            #pragma unroll
            for (int o = 16; o > 0; o >>= 1) a += __shfl_down_sync(0xffffffffu, a, o);
            if (tid == 0) {
                out[0] = -a * (0.69314718055994530942f / (float)MDATA);
                g_sync  = 0;   // reset for next graph replay
                g_count = 0;
            }
        }
    }
}

extern "C" void kernel_launch(void* const* d_in, const int* in_sizes, int n_in,
                              void* d_out, int out_size) {
    (void)in_sizes; (void)n_in; (void)out_size;
    bimm_fused_kernel<<<NBLK, TPB>>>(
        (const float*)d_in[0], (const float*)d_in[1], (const float*)d_in[2],
        (const float*)d_in[3], (const float*)d_in[4], (const float*)d_in[5],
        (const float*)d_in[6], (const float*)d_in[7], (const float*)d_in[8],
        (float*)d_out);
}

// round 7
// speedup vs baseline: 1.0033x; 1.0033x over previous
#include <cuda_runtime.h>
#include <math_constants.h>

#define MDATA 250000
#define NPH 4
#define NK 6
#define NMC 64
#define KN (NK*NMC)            // 384
#define NROWS (NPH+NK)

#define NUI 192
#define NVI 32
#define NUN (NUI+1)            // 193
#define NVN (NVI+1)            // 33
#define NODES (NUN*NVN)        // 6369 -> 99.5 KB table

#define V0C 0.01f
#define HUC (1.0f/192.0f)
#define HVC (0.3f/32.0f)

#define TPB 1024
#define NBLK 152               // = GB300 SM count; 1 block/SM (full RF)

__device__ float4 g_table[NODES];
__device__ float  g_partials[NBLK];
__device__ unsigned int g_sync  = 0;
__device__ unsigned int g_count = 0;

__device__ __forceinline__ float fex2(float x) {
    float y; asm("ex2.approx.ftz.f32 %0, %1;" : "=f"(y) : "f"(x)); return y;
}
__device__ __forceinline__ float flg2(float x) {
    float y; asm("lg2.approx.ftz.f32 %0, %1;" : "=f"(y) : "f"(x)); return y;
}
__device__ __forceinline__ float frcp(float x) {
    float y; asm("rcp.approx.ftz.f32 %0, %1;" : "=f"(y) : "f"(x)); return y;
}

// ---------------------------------------------------------------------------
// Single fused persistent kernel, MUFU-intrinsic hot paths:
//   phase 0: scalars in thread 0 -> shared; (k,n) constants by 384 threads
//   phase 1: grid-wide table build -> g_table, device spin barrier
//   phase 2: per-point bicubic Hermite from L1/L2 + fused deterministic reduce
// ---------------------------------------------------------------------------
__global__ void __launch_bounds__(TPB, 1) bimm_fused_kernel(
    const float* __restrict__ gu, const float* __restrict__ gv,
    const float* __restrict__ geps, const float* __restrict__ gI,
    const float* __restrict__ gW,  const float* __restrict__ gsb,
    const float* __restrict__ gsn, const float* __restrict__ gd,
    const float* __restrict__ gr,  float* __restrict__ out)
{
    __shared__ float4 skn[KN];     // (C_nats, A'*IE, C*IE, B_nats) per (k,n)
    __shared__ float4 sint4[NPH];  // (a*IE, b*IE, a_nats, 0) interior rows
    __shared__ float  sc[10];      // broadcast scalars
    __shared__ float  sRed[TPB / 32];
    __shared__ bool   s_last;

    const int tid  = threadIdx.x;
    const int wid  = tid >> 5;
    const int lane = tid & 31;
    const float IE = 1.44269504088896340736f;   // log2(e)

    // ---- scalar preamble: ONCE per block ----
    if (tid == 0) {
        float sb  = gsb[0];
        float sn  = gsn[0];
        float dd  = gd[0];
        float rho = tanhf(gr[0]);
        float omr = 1.0f - rho;
        float s2  = sn * sn * omr;
        float sr  = sn * sqrtf(omr);
        float isn2 = 1.0f / (sn * sn);

        float mw = -CUDART_INF_F;
        #pragma unroll
        for (int j = 0; j < NROWS; j++) mw = fmaxf(mw, gW[j]);
        float sw = 0.0f;
        #pragma unroll
        for (int j = 0; j < NROWS; j++) sw += expf(gW[j] - mw);
        float lse = mw + logf(sw);

        float cIn = 0.69314718056f + 0.12078223764f
                    - 3.0f * logf(sr) - logf(sn) - 0.5f * 1.83787706641f;
        float cCn = -logf(sn * sr * CUDART_PI_F * 1.41421356237f)
                    - logf((float)NMC);

        sc[0] = -0.5f * IE * isn2;   // k_u
        sc[1] = -IE / s2;            // k_v
        sc[2] = isn2;
        sc[3] = s2;
        sc[4] = cCn;
        sc[5] = cIn;
        sc[6] = lse;
        sc[7] = sb;
        sc[8] = dd;
    }
    __syncthreads();

    // ---- phase 0: per-(k,n) constants (384 threads) ----
    if (tid < KN) {
        float isn2 = sc[2], s2 = sc[3], cCn = sc[4], lse = sc[6];
        float sb = sc[7], dd = sc[8];
        float inv_s2 = frcp(s2);

        const int IAc[NK] = {0,0,0,1,1,2};
        const int IBc[NK] = {1,2,3,2,3,3};
        int k = tid >> 6;
        float Ia = gI[IAc[k]];
        float Ib = gI[IBc[k]];
        float dI = Ib - Ia;
        float gc = dI * rsqrtf(2.0f * CUDART_PI_F * sb * sb);
        float x  = geps[tid] * (2.0f * dd * sb) - dd * sb;
        float z  = x * frcp(1.41421356237309515f * sb);
        float In = (erff(z) + 1.0f) * 0.5f * dI + Ia;
        float G  = gc * fex2(-z * z * IE);       // erfinv(erf(z)) == z
        float B  = In * isn2;
        float Apn = -0.5f * In * In * isn2 - G * G * inv_s2
                    + cCn + (gW[NPH + k] - lse); // nats, minus log(G) below
        float Ap2 = Apn * IE - flg2(G);
        float C  = 2.0f * G * inv_s2;
        skn[tid] = make_float4(C, Ap2, C * IE, B);

        if (tid < NPH) {
            float cIn = sc[5];
            float Ip = gI[tid];
            float a = Ip * isn2;
            float b = -0.5f * Ip * Ip * isn2 + cIn + (gW[tid] - lse);
            sint4[tid] = make_float4(a * IE, b * IE, a, 0.0f);
        }
    }
    const float k_u = sc[0];
    const float k_v = sc[1];
    __syncthreads();

    // ---- phase 1: build table (one warp per node) ----
    for (int node = blockIdx.x * (TPB / 32) + wid; node < NODES;
         node += NBLK * (TPB / 32)) {
        int iu = node / NVN;
        int iv = node - iu * NVN;
        float u = iu * HUC;
        float v = V0C + iv * HVC;
        float inv_v = frcp(v);
        float uIE = u * IE;

        float sT = 0.f, sTu = 0.f, sTv = 0.f, sTuv = 0.f;
        #pragma unroll
        for (int t = 0; t < KN / 32; t++) {
            float4 c = skn[lane + (t << 5)];
            float qh  = fex2(fmaf(uIE, c.w, c.y));   // exp(uB + A')
            float xn  = c.z * v;                     // C*v (log2 units)
            float ex  = fex2(xn);
            float iex = frcp(ex);
            float sh  = ex - iex;                    // 2 sinh(Cv)
            float ch  = ex + iex;                    // 2 cosh(Cv)
            float tv  = fmaf(c.x, ch, -sh * inv_v);  // v*d/dv[2sinh(Cv)/v]
            float qs = qh * sh;
            float qt = qh * tv;
            sT   += qs;
            sTv  += qt;
            sTu  = fmaf(qs, c.w, sTu);
            sTuv = fmaf(qt, c.w, sTuv);
        }
        #pragma unroll
        for (int o = 16; o; o >>= 1) {
            sT   += __shfl_xor_sync(0xffffffffu, sT,   o);
            sTu  += __shfl_xor_sync(0xffffffffu, sTu,  o);
            sTv  += __shfl_xor_sync(0xffffffffu, sTv,  o);
            sTuv += __shfl_xor_sync(0xffffffffu, sTuv, o);
        }
        if (lane == 0) {
            float T   = sT   * inv_v;
            float Tu  = sTu  * inv_v;
            float Tv  = sTv  * inv_v;
            float Tuv = sTuv * inv_v;
            #pragma unroll
            for (int p = 0; p < NPH; p++) {
                float4 ab = sint4[p];
                float tp = fex2(fmaf(u, ab.x, ab.y));
                T  += tp;
                Tu = fmaf(ab.z, tp, Tu);
            }
            float invT = frcp(T);
            float hu = Tu * invT;
            float hv = Tv * invT;
            float4 o;
            o.x = flg2(T);
            o.y = hu * IE;
            o.z = hv * IE;
            o.w = (Tuv * invT - hu * hv) * IE;
            g_table[node] = o;
        }
    }

    // ---- device-wide barrier (all 152 blocks co-resident) ----
    if (tid == 0) {
        __threadfence();
        atomicAdd(&g_sync, 1u);
        while (atomicAdd(&g_sync, 0u) < NBLK) __nanosleep(64);
    }
    __syncthreads();
    __threadfence();

    // ---- phase 2: per-point bicubic Hermite ----
    float acc = 0.0f;
    for (int m = blockIdx.x * TPB + tid; m < MDATA; m += NBLK * TPB) {
        float u = gu[m];
        float v = gv[m];
        float l2v = flg2(v);
        float pm = k_u * u * u + k_v * v * v + 2.0f * l2v;

        float su = u * (float)NUI;
        int iu = (int)su; iu = min(max(iu, 0), NUI - 1);
        float s = su - (float)iu;
        float sv = (v - V0C) * ((float)NVI / 0.3f);
        int iv = (int)sv; iv = min(max(iv, 0), NVI - 1);
        float t = sv - (float)iv;

        const float4* tb = g_table + (iu * NVN + iv);
        float4 c00 = __ldg(tb);
        float4 c01 = __ldg(tb + 1);
        float4 c10 = __ldg(tb + NVN);
        float4 c11 = __ldg(tb + NVN + 1);

        float ss = s * s, s3 = ss * s;
        float Au0 = 2.0f * s3 - 3.0f * ss + 1.0f;
        float Au1 = (s3 - 2.0f * ss + s) * HUC;
        float Au2 = 3.0f * ss - 2.0f * s3;
        float Au3 = (s3 - ss) * HUC;
        float tt = t * t, t3 = tt * t;
        float Av0 = 2.0f * t3 - 3.0f * tt + 1.0f;
        float Av1 = (t3 - 2.0f * tt + t) * HVC;
        float Av2 = 3.0f * tt - 2.0f * t3;
        float Av3 = (t3 - tt) * HVC;

        float P0 = Av0*c00.x + Av1*c00.z + Av2*c01.x + Av3*c01.z;
        float P1 = Av0*c00.y + Av1*c00.w + Av2*c01.y + Av3*c01.w;
        float P2 = Av0*c10.x + Av1*c10.z + Av2*c11.x + Av3*c11.z;
        float P3 = Av0*c10.y + Av1*c10.w + Av2*c11.y + Av3*c11.w;
        float f  = Au0*P0 + Au1*P1 + Au2*P2 + Au3*P3;

        acc += pm + f;
    }

    // ---- deterministic block + grid reduction ----
    #pragma unroll
    for (int o = 16; o > 0; o >>= 1) acc += __shfl_down_sync(0xffffffffu, acc, o);
    if (lane == 0) sRed[wid] = acc;
    __syncthreads();
    if (tid == 0) {
        float bs = 0.0f;
        #pragma unroll
        for (int w = 0; w < TPB / 32; w++) bs += sRed[w];
        g_partials[blockIdx.x] = bs;
        __threadfence();
        unsigned int ticket = atomicAdd(&g_count, 1u);
        s_last = (ticket == NBLK - 1);
    }
    __syncthreads();

    if (s_last) {
        float a = 0.0f;
        if (tid < 32) {
            for (int i = tid; i < NBLK; i += 32) a += g_partials[i];
            #pragma unroll
            for (int o = 16; o > 0; o >>= 1) a += __shfl_down_sync(0xffffffffu, a, o);
            if (tid == 0) {
                out[0] = -a * (0.69314718055994530942f / (float)MDATA);
                g_sync  = 0;   // reset for next graph replay
                g_count = 0;
            }
        }
    }
}

extern "C" void kernel_launch(void* const* d_in, const int* in_sizes, int n_in,
                              void* d_out, int out_size) {
    (void)in_sizes; (void)n_in; (void)out_size;
    bimm_fused_kernel<<<NBLK, TPB>>>(
        (const float*)d_in[0], (const float*)d_in[1], (const float*)d_in[2],
        (const float*)d_in[3], (const float*)d_in[4], (const float*)d_in[5],
        (const float*)d_in[6], (const float*)d_in[7], (const float*)d_in[8],
        (float*)d_out);
}

// round 8
// speedup vs baseline: 1.1215x; 1.1178x over previous
#include <cuda_runtime.h>
#include <math_constants.h>

#define MDATA 250000
#define NPH 4
#define NK 6
#define NMC 64
#define KN (NK*NMC)            // 384
#define NROWS (NPH+NK)

#define NUI 96
#define NVI 32
#define NUN (NUI+1)            // 97
#define NVN (NVI+1)            // 33
#define NODES (NUN*NVN)        // 3201 -> 50 KB table

#define V0C 0.01f
#define HUC (1.0f/96.0f)
#define HVC (0.3f/32.0f)

#define TPB 512
#define NBLK 304               // 2 blocks/SM on 152 SMs; all co-resident

__device__ float4 g_table[NODES];
__device__ float  g_partials[NBLK];
__device__ unsigned int g_sync  = 0;
__device__ unsigned int g_count = 0;

__device__ __forceinline__ float fex2(float x) {
    float y; asm("ex2.approx.ftz.f32 %0, %1;" : "=f"(y) : "f"(x)); return y;
}
__device__ __forceinline__ float flg2(float x) {
    float y; asm("lg2.approx.ftz.f32 %0, %1;" : "=f"(y) : "f"(x)); return y;
}
__device__ __forceinline__ float frcp(float x) {
    float y; asm("rcp.approx.ftz.f32 %0, %1;" : "=f"(y) : "f"(x)); return y;
}

__global__ void __launch_bounds__(TPB, 2) bimm_fused_kernel(
    const float* __restrict__ gu, const float* __restrict__ gv,
    const float* __restrict__ geps, const float* __restrict__ gI,
    const float* __restrict__ gW,  const float* __restrict__ gsb,
    const float* __restrict__ gsn, const float* __restrict__ gd,
    const float* __restrict__ gr,  float* __restrict__ out)
{
    __shared__ float4 skn[KN];     // (C_nats, A'*IE, C*IE, B_nats)
    __shared__ float4 sint4[NPH];  // (a*IE, b*IE, a_nats, 0)
    __shared__ float  sc[10];
    __shared__ float  sRed[TPB / 32];
    __shared__ bool   s_last;

    const int tid  = threadIdx.x;
    const int wid  = tid >> 5;
    const int lane = tid & 31;
    const float IE = 1.44269504088896340736f;   // log2(e)

    // ---- scalar preamble once per block ----
    if (tid == 0) {
        float sb  = gsb[0];
        float sn  = gsn[0];
        float dd  = gd[0];
        float rho = tanhf(gr[0]);
        float omr = 1.0f - rho;
        float s2  = sn * sn * omr;
        float sr  = sn * sqrtf(omr);
        float isn2 = 1.0f / (sn * sn);

        float mw = -CUDART_INF_F;
        #pragma unroll
        for (int j = 0; j < NROWS; j++) mw = fmaxf(mw, gW[j]);
        float sw = 0.0f;
        #pragma unroll
        for (int j = 0; j < NROWS; j++) sw += expf(gW[j] - mw);
        float lse = mw + logf(sw);

        float cIn = 0.69314718056f + 0.12078223764f
                    - 3.0f * logf(sr) - logf(sn) - 0.5f * 1.83787706641f;
        float cCn = -logf(sn * sr * CUDART_PI_F * 1.41421356237f)
                    - logf((float)NMC);

        sc[0] = -0.5f * IE * isn2;   // k_u
        sc[1] = -IE / s2;            // k_v
        sc[2] = isn2;
        sc[3] = s2;
        sc[4] = cCn;
        sc[5] = cIn;
        sc[6] = lse;
        sc[7] = sb;
        sc[8] = dd;
    }
    __syncthreads();

    // ---- phase 0: (k,n) constants ----
    if (tid < KN) {
        float isn2 = sc[2], s2 = sc[3], cCn = sc[4], lse = sc[6];
        float sb = sc[7], dd = sc[8];
        float inv_s2 = frcp(s2);

        const int IAc[NK] = {0,0,0,1,1,2};
        const int IBc[NK] = {1,2,3,2,3,3};
        int k = tid >> 6;
        float Ia = gI[IAc[k]];
        float Ib = gI[IBc[k]];
        float dI = Ib - Ia;
        float gc = dI * rsqrtf(2.0f * CUDART_PI_F * sb * sb);
        float x  = geps[tid] * (2.0f * dd * sb) - dd * sb;
        float z  = x * frcp(1.41421356237309515f * sb);
        float In = (erff(z) + 1.0f) * 0.5f * dI + Ia;
        float G  = gc * fex2(-z * z * IE);       // erfinv(erf(z)) == z
        float B  = In * isn2;
        float Apn = -0.5f * In * In * isn2 - G * G * inv_s2
                    + cCn + (gW[NPH + k] - lse);
        float Ap2 = Apn * IE - flg2(G);
        float C  = 2.0f * G * inv_s2;
        skn[tid] = make_float4(C, Ap2, C * IE, B);

        if (tid < NPH) {
            float cIn = sc[5];
            float Ip = gI[tid];
            float a = Ip * isn2;
            float b = -0.5f * Ip * Ip * isn2 + cIn + (gW[tid] - lse);
            sint4[tid] = make_float4(a * IE, b * IE, a, 0.0f);
        }
    }
    const float k_u = sc[0];
    const float k_v = sc[1];
    __syncthreads();

    // ---- phase 1: build table (<= 1 node per warp; 4864 warps, 3201 nodes) ----
    {
        int node = blockIdx.x * (TPB / 32) + wid;
        if (node < NODES) {
            int iu = node / NVN;
            int iv = node - iu * NVN;
            float u = iu * HUC;
            float v = V0C + iv * HVC;
            float inv_v = frcp(v);
            float uIE = u * IE;

            float sT = 0.f, sTu = 0.f, sTv = 0.f, sTuv = 0.f;
            #pragma unroll
            for (int t = 0; t < KN / 32; t++) {
                float4 c = skn[lane + (t << 5)];
                float qh  = fex2(fmaf(uIE, c.w, c.y));
                float xn  = c.z * v;
                float ex  = fex2(xn);
                float iex = frcp(ex);
                float sh  = ex - iex;                   // 2 sinh(Cv)
                float ch  = ex + iex;                   // 2 cosh(Cv)
                float tv  = fmaf(c.x, ch, -sh * inv_v);
                float qs = qh * sh;
                float qt = qh * tv;
                sT   += qs;
                sTv  += qt;
                sTu  = fmaf(qs, c.w, sTu);
                sTuv = fmaf(qt, c.w, sTuv);
            }
            #pragma unroll
            for (int o = 16; o; o >>= 1) {
                sT   += __shfl_xor_sync(0xffffffffu, sT,   o);
                sTu  += __shfl_xor_sync(0xffffffffu, sTu,  o);
                sTv  += __shfl_xor_sync(0xffffffffu, sTv,  o);
                sTuv += __shfl_xor_sync(0xffffffffu, sTuv, o);
            }
            if (lane == 0) {
                float T   = sT   * inv_v;
                float Tu  = sTu  * inv_v;
                float Tv  = sTv  * inv_v;
                float Tuv = sTuv * inv_v;
                #pragma unroll
                for (int p = 0; p < NPH; p++) {
                    float4 ab = sint4[p];
                    float tp = fex2(fmaf(u, ab.x, ab.y));
                    T  += tp;
                    Tu = fmaf(ab.z, tp, Tu);
                }
                float invT = frcp(T);
                float hu = Tu * invT;
                float hv = Tv * invT;
                float4 o;
                o.x = flg2(T);
                o.y = hu * IE;
                o.z = hv * IE;
                o.w = (Tuv * invT - hu * hv) * IE;
                g_table[node] = o;
            }
        }
    }

    // ---- device-wide barrier (304 blocks, all co-resident) ----
    if (tid == 0) {
        __threadfence();
        atomicAdd(&g_sync, 1u);
        while (atomicAdd(&g_sync, 0u) < NBLK) __nanosleep(64);
    }
    __syncthreads();
    __threadfence();

    // ---- phase 2: 2 points per thread (float2), single pass ----
    float acc = 0.0f;
    {
        int idx = blockIdx.x * TPB + tid;          // pair index
        int m0 = idx * 2;
        if (m0 < MDATA) {
            float2 u2 = __ldg((const float2*)gu + idx);
            float2 v2 = __ldg((const float2*)gv + idx);
            #pragma unroll
            for (int i = 0; i < 2; i++) {
                float u = (i == 0) ? u2.x : u2.y;
                float v = (i == 0) ? v2.x : v2.y;
                float l2v = flg2(v);
                float pm = k_u * u * u + k_v * v * v + 2.0f * l2v;

                float su = u * (float)NUI;
                int iu = (int)su; iu = min(max(iu, 0), NUI - 1);
                float s = su - (float)iu;
                float sv = (v - V0C) * ((float)NVI / 0.3f);
                int iv = (int)sv; iv = min(max(iv, 0), NVI - 1);
                float t = sv - (float)iv;

                const float4* tb = g_table + (iu * NVN + iv);
                float4 c00 = __ldg(tb);
                float4 c01 = __ldg(tb + 1);
                float4 c10 = __ldg(tb + NVN);
                float4 c11 = __ldg(tb + NVN + 1);

                float ss = s * s, s3 = ss * s;
                float Au0 = 2.0f * s3 - 3.0f * ss + 1.0f;
                float Au1 = (s3 - 2.0f * ss + s) * HUC;
                float Au2 = 3.0f * ss - 2.0f * s3;
                float Au3 = (s3 - ss) * HUC;
                float tt = t * t, t3 = tt * t;
                float Av0 = 2.0f * t3 - 3.0f * tt + 1.0f;
                float Av1 = (t3 - 2.0f * tt + t) * HVC;
                float Av2 = 3.0f * tt - 2.0f * t3;
                float Av3 = (t3 - tt) * HVC;

                float P0 = Av0*c00.x + Av1*c00.z + Av2*c01.x + Av3*c01.z;
                float P1 = Av0*c00.y + Av1*c00.w + Av2*c01.y + Av3*c01.w;
                float P2 = Av0*c10.x + Av1*c10.z + Av2*c11.x + Av3*c11.z;
                float P3 = Av0*c10.y + Av1*c10.w + Av2*c11.y + Av3*c11.w;
                float f  = Au0*P0 + Au1*P1 + Au2*P2 + Au3*P3;

                acc += pm + f;
            }
        }
    }

    // ---- deterministic block + grid reduction ----
    #pragma unroll
    for (int o = 16; o > 0; o >>= 1) acc += __shfl_down_sync(0xffffffffu, acc, o);
    if (lane == 0) sRed[wid] = acc;
    __syncthreads();
    if (tid == 0) {
        float bs = 0.0f;
        #pragma unroll
        for (int w = 0; w < TPB / 32; w++) bs += sRed[w];
        g_partials[blockIdx.x] = bs;
        __threadfence();
        unsigned int ticket = atomicAdd(&g_count, 1u);
        s_last = (ticket == NBLK - 1);
    }
    __syncthreads();

    if (s_last) {
        float a = 0.0f;
        if (tid < 32) {
            for (int i = tid; i < NBLK; i += 32) a += g_partials[i];
            #pragma unroll
            for (int o = 16; o > 0; o >>= 1) a += __shfl_down_sync(0xffffffffu, a, o);
            if (tid == 0) {
                out[0] = -a * (0.69314718055994530942f / (float)MDATA);
                g_sync  = 0;   // reset for next graph replay
                g_count = 0;
            }
        }
    }
}

extern "C" void kernel_launch(void* const* d_in, const int* in_sizes, int n_in,
                              void* d_out, int out_size) {
    (void)in_sizes; (void)n_in; (void)out_size;
    bimm_fused_kernel<<<NBLK, TPB>>>(
        (const float*)d_in[0], (const float*)d_in[1], (const float*)d_in[2],
        (const float*)d_in[3], (const float*)d_in[4], (const float*)d_in[5],
        (const float*)d_in[6], (const float*)d_in[7], (const float*)d_in[8],
        (float*)d_out);
}

// round 9
// speedup vs baseline: 1.1364x; 1.0133x over previous
#include <cuda_runtime.h>
#include <math_constants.h>

#define MDATA 250000
#define NPH 4
#define NK 6
#define NMC 64
#define KN (NK*NMC)            // 384
#define NROWS (NPH+NK)

#define NUI 96
#define NVI 32
#define NUN (NUI+1)            // 97
#define NVN (NVI+1)            // 33
#define NODES (NUN*NVN)        // 3201 -> 50 KB table

#define V0C 0.01f
#define HUC (1.0f/96.0f)
#define HVC (0.3f/32.0f)

#define TPB 512
#define OCC 3
#define NBLK (152*OCC)         // 456 blocks, 3/SM, all co-resident

__device__ float4 g_table[NODES];
__device__ float  g_partials[NBLK];
__device__ unsigned int g_sync  = 0;
__device__ unsigned int g_count = 0;

__device__ __forceinline__ float fex2(float x) {
    float y; asm("ex2.approx.ftz.f32 %0, %1;" : "=f"(y) : "f"(x)); return y;
}
__device__ __forceinline__ float flg2(float x) {
    float y; asm("lg2.approx.ftz.f32 %0, %1;" : "=f"(y) : "f"(x)); return y;
}
__device__ __forceinline__ float frcp(float x) {
    float y; asm("rcp.approx.ftz.f32 %0, %1;" : "=f"(y) : "f"(x)); return y;
}
__device__ __forceinline__ unsigned int ld_acq(const unsigned int* p) {
    unsigned int v;
    asm volatile("ld.global.acquire.gpu.u32 %0, [%1];" : "=r"(v) : "l"(p));
    return v;
}

__global__ void __launch_bounds__(TPB, OCC) bimm_fused_kernel(
    const float* __restrict__ gu, const float* __restrict__ gv,
    const float* __restrict__ geps, const float* __restrict__ gI,
    const float* __restrict__ gW,  const float* __restrict__ gsb,
    const float* __restrict__ gsn, const float* __restrict__ gd,
    const float* __restrict__ gr,  float* __restrict__ out)
{
    __shared__ float4 skn[KN];     // (C_nats, A'*IE, C*IE, B_nats)
    __shared__ float4 sint4[NPH];  // (a*IE, b*IE, a_nats, 0)
    __shared__ float  sRed[TPB / 32];
    __shared__ bool   s_last;

    const int tid  = threadIdx.x;
    const int wid  = tid >> 5;
    const int lane = tid & 31;
    const float IE  = 1.44269504088896340736f;  // log2(e)
    const float LN2 = 0.69314718055994530942f;

    // ---- preamble: every thread, all-MUFU (no serial chain, no sync) ----
    const float sb  = gsb[0];
    const float sn  = gsn[0];
    const float dd  = gd[0];
    const float r0  = gr[0];
    // tanh(r) = 1 - 2/(exp(2r)+1)
    const float rho = 1.0f - 2.0f * frcp(fex2(2.0f * r0 * IE) + 1.0f);
    const float omr = 1.0f - rho;
    const float s2  = sn * sn * omr;
    const float isn2 = frcp(sn * sn);
    const float inv_s2 = frcp(s2);
    const float l2sn = flg2(sn);
    const float l2s2 = flg2(s2);
    const float k_u = -0.5f * IE * isn2;
    const float k_v = -IE * inv_s2;

    // log-softmax normalizer (log2 units)
    float mw = gW[0];
    #pragma unroll
    for (int j = 1; j < NROWS; j++) mw = fmaxf(mw, gW[j]);
    float sw = 0.0f;
    #pragma unroll
    for (int j = 0; j < NROWS; j++) sw += fex2((gW[j] - mw) * IE);
    const float lse2 = mw * IE + flg2(sw);      // log2 sum exp W

    // ln sr = ln sn + 0.5 ln omr ; use log2 domain
    const float l2sr = l2sn + 0.5f * flg2(omr);
    // interior const (log2): ln2 + lnGamma(1.5) stuff
    const float cIn2 = IE * (0.69314718056f + 0.12078223764f
                             - 0.5f * 1.83787706641f)
                       - 3.0f * l2sr - l2sn;
    // interface const (log2): -ln(sn*sr*pi*sqrt2) - ln NMC
    const float cCn2 = -(l2sn + l2sr + IE * (1.14472988585f + 0.34657359028f))
                       - 6.0f;                  // log2(64) = 6
    // 1.14472988585 = ln(pi); 0.34657359 = 0.5 ln 2

    // ---- phase 0: (k,n) constants ----
    if (tid < KN) {
        const int IAc[NK] = {0,0,0,1,1,2};
        const int IBc[NK] = {1,2,3,2,3,3};
        int k = tid >> 6;
        float Ia = gI[IAc[k]];
        float Ib = gI[IBc[k]];
        float dI = Ib - Ia;
        float gc = dI * rsqrtf(2.0f * CUDART_PI_F * sb * sb);
        float x  = geps[tid] * (2.0f * dd * sb) - dd * sb;
        float z  = x * frcp(1.41421356237309515f * sb);
        float In = (erff(z) + 1.0f) * 0.5f * dI + Ia;
        float G  = gc * fex2(-z * z * IE);      // erfinv(erf(z)) == z
        float B  = In * isn2;
        float Ap2 = (-0.5f * In * In * isn2 - G * G * inv_s2) * IE
                    + cCn2 + (gW[NPH + k] * IE - lse2) - flg2(G);
        float C  = 2.0f * G * inv_s2;
        skn[tid] = make_float4(C, Ap2, C * IE, B);

        if (tid < NPH) {
            float Ip = gI[tid];
            float a = Ip * isn2;
            float b2 = -0.5f * Ip * Ip * isn2 * IE + cIn2
                       + (gW[tid] * IE - lse2);
            sint4[tid] = make_float4(a * IE, b2, a, 0.0f);
        }
    }
    __syncthreads();

    // ---- phase 1: build table (grid-split, <=1 node/warp) ----
    {
        int node = blockIdx.x * (TPB / 32) + wid;
        if (node < NODES) {
            int iu = node / NVN;
            int iv = node - iu * NVN;
            float u = iu * HUC;
            float v = V0C + iv * HVC;
            float inv_v = frcp(v);
            float uIE = u * IE;

            float sT = 0.f, sTu = 0.f, sTv = 0.f, sTuv = 0.f;
            #pragma unroll
            for (int t = 0; t < KN / 32; t++) {
                float4 c = skn[lane + (t << 5)];
                float qh  = fex2(fmaf(uIE, c.w, c.y));
                float xn  = c.z * v;
                float ex  = fex2(xn);
                float iex = frcp(ex);
                float sh  = ex - iex;
                float ch  = ex + iex;
                float tv  = fmaf(c.x, ch, -sh * inv_v);
                float qs = qh * sh;
                float qt = qh * tv;
                sT   += qs;
                sTv  += qt;
                sTu  = fmaf(qs, c.w, sTu);
                sTuv = fmaf(qt, c.w, sTuv);
            }
            #pragma unroll
            for (int o = 16; o; o >>= 1) {
                sT   += __shfl_xor_sync(0xffffffffu, sT,   o);
                sTu  += __shfl_xor_sync(0xffffffffu, sTu,  o);
                sTv  += __shfl_xor_sync(0xffffffffu, sTv,  o);
                sTuv += __shfl_xor_sync(0xffffffffu, sTuv, o);
            }
            if (lane == 0) {
                float T   = sT   * inv_v;
                float Tu  = sTu  * inv_v;
                float Tv  = sTv  * inv_v;
                float Tuv = sTuv * inv_v;
                #pragma unroll
                for (int p = 0; p < NPH; p++) {
                    float4 ab = sint4[p];
                    float tp = fex2(fmaf(u, ab.x, ab.y));
                    T  += tp;
                    Tu = fmaf(ab.z, tp, Tu);
                }
                float invT = frcp(T);
                float hu = Tu * invT;
                float hv = Tv * invT;
                float4 o;
                o.x = flg2(T);
                o.y = hu * IE;
                o.z = hv * IE;
                o.w = (Tuv * invT - hu * hv) * IE;
                g_table[node] = o;
            }
        }
    }

    // ---- prefetch phase-2 inputs BEFORE the grid barrier ----
    const int idx = blockIdx.x * TPB + tid;     // pair index
    const bool havept = (idx * 2 < MDATA);
    float2 u2 = make_float2(0.5f, 0.5f);
    float2 v2 = make_float2(0.1f, 0.1f);
    if (havept) {
        u2 = __ldg((const float2*)gu + idx);
        v2 = __ldg((const float2*)gv + idx);
    }

    // ---- device-wide barrier (456 co-resident blocks) ----
    if (tid == 0) {
        __threadfence();
        atomicAdd(&g_sync, 1u);
        while (ld_acq(&g_sync) < NBLK) __nanosleep(32);
    }
    __syncthreads();

    // ---- phase 2: 2 points per thread ----
    float acc = 0.0f;
    if (havept) {
        #pragma unroll
        for (int i = 0; i < 2; i++) {
            float u = (i == 0) ? u2.x : u2.y;
            float v = (i == 0) ? v2.x : v2.y;
            float l2v = flg2(v);
            float pm = k_u * u * u + k_v * v * v + 2.0f * l2v;

            float su = u * (float)NUI;
            int iu = (int)su; iu = min(max(iu, 0), NUI - 1);
            float s = su - (float)iu;
            float sv = (v - V0C) * ((float)NVI / 0.3f);
            int iv = (int)sv; iv = min(max(iv, 0), NVI - 1);
            float t = sv - (float)iv;

            const float4* tb = g_table + (iu * NVN + iv);
            float4 c00 = __ldg(tb);
            float4 c01 = __ldg(tb + 1);
            float4 c10 = __ldg(tb + NVN);
            float4 c11 = __ldg(tb + NVN + 1);

            float ss = s * s, s3 = ss * s;
            float Au0 = 2.0f * s3 - 3.0f * ss + 1.0f;
            float Au1 = (s3 - 2.0f * ss + s) * HUC;
            float Au2 = 3.0f * ss - 2.0f * s3;
            float Au3 = (s3 - ss) * HUC;
            float tt = t * t, t3 = tt * t;
            float Av0 = 2.0f * t3 - 3.0f * tt + 1.0f;
            float Av1 = (t3 - 2.0f * tt + t) * HVC;
            float Av2 = 3.0f * tt - 2.0f * t3;
            float Av3 = (t3 - tt) * HVC;

            float P0 = Av0*c00.x + Av1*c00.z + Av2*c01.x + Av3*c01.z;
            float P1 = Av0*c00.y + Av1*c00.w + Av2*c01.y + Av3*c01.w;
            float P2 = Av0*c10.x + Av1*c10.z + Av2*c11.x + Av3*c11.z;
            float P3 = Av0*c10.y + Av1*c10.w + Av2*c11.y + Av3*c11.w;
            float f  = Au0*P0 + Au1*P1 + Au2*P2 + Au3*P3;

            acc += pm + f;
        }
    }

    // ---- deterministic block + grid reduction ----
    #pragma unroll
    for (int o = 16; o > 0; o >>= 1) acc += __shfl_down_sync(0xffffffffu, acc, o);
    if (lane == 0) sRed[wid] = acc;
    __syncthreads();
    if (tid == 0) {
        float bs = 0.0f;
        #pragma unroll
        for (int w = 0; w < TPB / 32; w++) bs += sRed[w];
        g_partials[blockIdx.x] = bs;
        __threadfence();
        unsigned int ticket = atomicAdd(&g_count, 1u);
        s_last = (ticket == NBLK - 1);
    }
    __syncthreads();

    if (s_last) {
        float a = 0.0f;
        if (tid < 32) {
            for (int i = tid; i < NBLK; i += 32) a += g_partials[i];
            #pragma unroll
            for (int o = 16; o > 0; o >>= 1) a += __shfl_down_sync(0xffffffffu, a, o);
            if (tid == 0) {
                out[0] = -a * (LN2 / (float)MDATA);
                g_sync  = 0;   // reset for next graph replay
                g_count = 0;
            }
        }
    }
}

extern "C" void kernel_launch(void* const* d_in, const int* in_sizes, int n_in,
                              void* d_out, int out_size) {
    (void)in_sizes; (void)n_in; (void)out_size;
    bimm_fused_kernel<<<NBLK, TPB>>>(
        (const float*)d_in[0], (const float*)d_in[1], (const float*)d_in[2],
        (const float*)d_in[3], (const float*)d_in[4], (const float*)d_in[5],
        (const float*)d_in[6], (const float*)d_in[7], (const float*)d_in[8],
        (float*)d_out);
}